// round 11
// baseline (speedup 1.0000x reference)
#include <cuda_runtime.h>
#include <math.h>

// ---------------------------------------------------------------------------
// TAM forward, GB300.  Shapes fixed: b=8, t=16, c=256, h=w=28 (784 px).
//   x   : [8,16,256,28,28] f32
//   W1  : [32,16]   W2 : [7,32]   Wl1 : [64,256,7]   Wl2 : [256,64,1]
//   out : [128,256,28,28] f32
// Pipeline (2 launches): pool+conv1 (trailing-ticket fusion) -> main
// ---------------------------------------------------------------------------

#define B     8
#define T     16
#define C     256
#define HW4   196            // float4 per plane
#define SLAB  50176          // float4 per (b,t) slab  = C*HW4
#define CO    64             // c/4

#define NPOOL   4096         // pool blocks
#define NTRAIL  64           // trailing blocks that run conv1
#define NUNITS  512          // conv1 (b,o) units  = 8*64

__device__ float g_pooled[B * C * T];      // [b,c,t]
__device__ float g_y[B * CO * T];          // [b,o,t]
__device__ unsigned int g_ctr;             // completion counter (memset to 0)

// ---------------------------------------------------------------------------
// Kernel 1: pool (one warp per plane) + conv1 on the 64 trailing blocks.
// grid = 4096, block = 256.  regs pinned <=32 to keep 8 blocks/SM.
// ---------------------------------------------------------------------------
__global__ void __launch_bounds__(256, 8) pool_conv_kernel(const float* __restrict__ x,
                                                           const float* __restrict__ Wl1) {
    __shared__ unsigned s_ticket;
    __shared__ float sm[8][T];

    const int warp = threadIdx.x >> 5;
    const int lane = threadIdx.x & 31;

    // ---- pooling: p = (b*16+t)*256 + c ----
    {
        const int p = blockIdx.x * 8 + warp;
        const float4* xp = reinterpret_cast<const float4*>(x) + (size_t)p * HW4;
        float s = 0.f;
#pragma unroll
        for (int j = 0; j < 7; j++) {
            int idx = lane + 32 * j;
            if (idx < HW4) {
                float4 v = xp[idx];
                s += (v.x + v.y) + (v.z + v.w);
            }
        }
#pragma unroll
        for (int off = 16; off; off >>= 1) s += __shfl_xor_sync(0xFFFFFFFFu, s, off);
        if (lane == 0) {
            int c = p & 255;
            int bt = p >> 8;
            int t = bt & 15;
            int b = bt >> 4;
            g_pooled[(b * C + c) * T + t] = s * (1.f / 784.f);
        }
    }
    __syncthreads();

    // ---- ticket: publish our pooled rows, count completion ----
    if (threadIdx.x == 0) {
        __threadfence();
        s_ticket = atomicAdd(&g_ctr, 1u);
    }
    __syncthreads();
    const unsigned ticket = s_ticket;
    if (ticket < NPOOL - NTRAIL) return;

    // ---- trailing blocks: wait for ALL pooled writes, then run conv1 ----
    if (threadIdx.x == 0) {
        while (atomicCAS(&g_ctr, (unsigned)NPOOL, (unsigned)NPOOL) != (unsigned)NPOOL) {
            __nanosleep(64);
        }
    }
    __syncthreads();
    __threadfence();

    const int i = threadIdx.x;               // input channel
    const int base_unit = (int)(ticket - (NPOOL - NTRAIL)) * (NUNITS / NTRAIL);

#pragma unroll 1
    for (int u = 0; u < NUNITS / NTRAIL; u++) {
        const int unit = base_unit + u;
        const int b = unit >> 6;
        const int o = unit & 63;

        const float* pr = &g_pooled[(b * C + i) * T];
        const float* w  = &Wl1[(o * C + i) * 7];
        float wk[7];
#pragma unroll
        for (int k = 0; k < 7; k++) wk[k] = w[k];

        // two halves of t to keep register pressure low
#pragma unroll 1
        for (int h = 0; h < 2; h++) {
            float pp[14];
#pragma unroll
            for (int t = 0; t < 14; t++) {
                int tt = h * 8 + t - 3;
                pp[t] = (tt >= 0 && tt < T) ? pr[tt] : 0.f;
            }
            float acc[8];
#pragma unroll
            for (int t = 0; t < 8; t++) {
                float s2 = 0.f;
#pragma unroll
                for (int k = 0; k < 7; k++) s2 = fmaf(wk[k], pp[t + k], s2);
                acc[t] = s2;
            }
#pragma unroll
            for (int off = 16; off; off >>= 1) {
#pragma unroll
                for (int t = 0; t < 8; t++) acc[t] += __shfl_xor_sync(0xFFFFFFFFu, acc[t], off);
            }
            if (lane < 8) sm[warp][h * 8 + lane] = acc[lane];
        }
        __syncthreads();
        if (i < T) {
            float s = 0.f;
#pragma unroll
            for (int w2 = 0; w2 < 8; w2++) s += sm[w2][i];
            g_y[(b * CO + o) * T + i] = tanhf(s);
        }
        __syncthreads();
    }
}

// ---------------------------------------------------------------------------
// Kernel 2: gate (fused) + gated depthwise temporal conv.
// Flat mapping: column s = c*196 + pix within a b.  256 cols per block.
// grid = 8 * 196 = 1568 blocks (reversed for L2 reuse of pool's tail),
// block = 256 threads.  Warps 0-2 compute gate for the <=3 channels spanned.
// ---------------------------------------------------------------------------
__global__ void __launch_bounds__(256) tam_main_kernel(const float* __restrict__ x,
                                                       const float* __restrict__ W1,
                                                       const float* __restrict__ W2,
                                                       const float* __restrict__ Wl2,
                                                       float* __restrict__ out) {
    const int blk = (int)gridDim.x - 1 - blockIdx.x;   // reverse order
    const int b  = blk / 196;
    const int j  = blk - b * 196;
    const int s0 = j * 256;
    const int c_first = s0 / HW4;

    __shared__ float sk[3][8];    // kernel[ci][k]
    __shared__ float sl[3][T];    // local[ci][t]

    const int warp = threadIdx.x >> 5;
    const int lane = threadIdx.x & 31;

    if (warp < 3) {
        const int c = c_first + warp;
        if (c < C) {
            float p = (lane < T) ? g_pooled[(b * C + c) * T + lane] : 0.f;

            // --- G branch: 7-tap softmax kernel ---
            float g = 0.f;
#pragma unroll
            for (int t = 0; t < T; t++) {
                float pt = __shfl_sync(0xFFFFFFFFu, p, t);
                g = fmaf(W1[lane * T + t], pt, g);
            }
            g = tanhf(g);

            float lg[7];
#pragma unroll
            for (int k = 0; k < 7; k++) {
                float s = W2[k * 32 + lane] * g;
#pragma unroll
                for (int off = 16; off; off >>= 1) s += __shfl_xor_sync(0xFFFFFFFFu, s, off);
                lg[k] = s;
            }
            float m = lg[0];
#pragma unroll
            for (int k = 1; k < 7; k++) m = fmaxf(m, lg[k]);
            float den = 0.f;
#pragma unroll
            for (int k = 0; k < 7; k++) { lg[k] = expf(lg[k] - m); den += lg[k]; }
            float inv = 1.f / den;
            if (lane < 7) sk[warp][lane] = lg[lane] * inv;

            // --- L branch: sigmoid( Wl2[c,:] . y[b,:,t] ) ---
            if (lane < T) {
                const float* yb = &g_y[b * CO * T];
                const float* wr = &Wl2[c * CO];
                float acc = 0.f;
#pragma unroll
                for (int o = 0; o < CO; o++)
                    acc = fmaf(wr[o], yb[o * T + lane], acc);
                sl[warp][lane] = 1.f / (1.f + expf(-acc));
            }
        }
    }
    __syncthreads();

    const int s  = s0 + threadIdx.x;        // column within b-slab
    const int c  = s / HW4;                 // constant divisor -> mul/shift
    const int ci = c - c_first;             // 0..2

    float ker[7], loc[T];
#pragma unroll
    for (int k = 0; k < 7; k++) ker[k] = sk[ci][k];
#pragma unroll
    for (int t = 0; t < T; t++) loc[t] = sl[ci][t];

    const size_t base = (size_t)(b * T) * SLAB + s;    // float4 index of (b,t=0,s)
    const float4* xp = reinterpret_cast<const float4*>(x);
    float4* op = reinterpret_cast<float4*>(out);

    float4 gt[T];
#pragma unroll
    for (int t = 0; t < T; t++) {
        float4 v = xp[base + (size_t)t * SLAB];
        float lt = loc[t];
        gt[t].x = v.x * lt; gt[t].y = v.y * lt;
        gt[t].z = v.z * lt; gt[t].w = v.w * lt;
    }
#pragma unroll
    for (int to = 0; to < T; to++) {
        float4 a = make_float4(0.f, 0.f, 0.f, 0.f);
#pragma unroll
        for (int k = 0; k < 7; k++) {
            int tt = to + k - 3;
            if (tt >= 0 && tt < T) {          // compile-time resolved
                float kv = ker[k];
                a.x = fmaf(kv, gt[tt].x, a.x);
                a.y = fmaf(kv, gt[tt].y, a.y);
                a.z = fmaf(kv, gt[tt].z, a.z);
                a.w = fmaf(kv, gt[tt].w, a.w);
            }
        }
        __stcs(&op[base + (size_t)to * SLAB], a);      // evict-first store
    }
}

// ---------------------------------------------------------------------------
extern "C" void kernel_launch(void* const* d_in, const int* in_sizes, int n_in,
                              void* d_out, int out_size) {
    const float* x   = (const float*)d_in[0];
    const float* W1  = (const float*)d_in[1];
    const float* W2  = (const float*)d_in[2];
    const float* Wl1 = (const float*)d_in[3];
    const float* Wl2 = (const float*)d_in[4];
    float* out = (float*)d_out;

    // reset completion counter (graph-capturable, no allocation)
    void* ctr_addr = nullptr;
    cudaGetSymbolAddress(&ctr_addr, g_ctr);
    cudaMemsetAsync(ctr_addr, 0, sizeof(unsigned int));

    pool_conv_kernel<<<NPOOL, 256>>>(x, Wl1);                 // pool + conv1
    tam_main_kernel<<<B * 196, 256>>>(x, W1, W2, Wl2, out);   // gate + dw-conv
}

// round 16
// speedup vs baseline: 1.7111x; 1.7111x over previous
#include <cuda_runtime.h>
#include <math.h>

// ---------------------------------------------------------------------------
// TAM forward, GB300.  Shapes fixed: b=8, t=16, c=256, h=w=28 (784 px).
//   x   : [8,16,256,28,28] f32
//   W1  : [32,16]   W2 : [7,32]   Wl1 : [64,256,7]   Wl2 : [256,64,1]
//   out : [128,256,28,28] f32
// Pipeline (4 launches): pool -> conv1 -> gate -> main (loads-only prologue)
// ---------------------------------------------------------------------------

#define B     8
#define T     16
#define C     256
#define HW4   196            // float4 per plane
#define SLAB  50176          // float4 per (b,t) slab  = C*HW4
#define CO    64             // c/4

__device__ float g_pooled[B * C * T];      // [b,c,t]
__device__ float g_y[B * CO * T];          // [b,o,t]
__device__ float g_ker[B * C * 8];         // [b,c,k] (k padded to 8)
__device__ float g_loc[B * C * T];         // [b,c,t]

// ---------------------------------------------------------------------------
// Kernel 1: pooled[b,c,t] = mean_{hw} x[b,t,c,hw].  One warp per plane.
// Measured: 19.5us, DRAM 69%, occ 86% -- at roofline, do not touch.
// ---------------------------------------------------------------------------
__global__ void __launch_bounds__(256) pool_kernel(const float* __restrict__ x) {
    const int warp = threadIdx.x >> 5;
    const int lane = threadIdx.x & 31;
    const int p = blockIdx.x * 8 + warp;           // p = (b*16+t)*256 + c
    const float4* xp = reinterpret_cast<const float4*>(x) + (size_t)p * HW4;

    float s = 0.f;
#pragma unroll
    for (int j = 0; j < 7; j++) {
        int idx = lane + 32 * j;
        if (idx < HW4) {
            float4 v = xp[idx];
            s += (v.x + v.y) + (v.z + v.w);
        }
    }
#pragma unroll
    for (int off = 16; off; off >>= 1) s += __shfl_xor_sync(0xFFFFFFFFu, s, off);

    if (lane == 0) {
        int c = p & 255;
        int bt = p >> 8;
        int t = bt & 15;
        int b = bt >> 4;
        g_pooled[(b * C + c) * T + t] = s * (1.f / 784.f);
    }
}

// ---------------------------------------------------------------------------
// Kernel 2: y[b,o,t] = tanh( sum_{i,k} Wl1[o,i,k] * pooled_pad[b,i,t+k-3] )
// grid = b*64 = 512 blocks, 256 threads (one thread per input channel i).
// ---------------------------------------------------------------------------
__global__ void __launch_bounds__(256) conv1_kernel(const float* __restrict__ Wl1) {
    const int b = blockIdx.x >> 6;
    const int o = blockIdx.x & 63;
    const int i = threadIdx.x;

    const float* pr = &g_pooled[(b * C + i) * T];
    float pp[T + 6];
#pragma unroll
    for (int t = 0; t < T + 6; t++) {
        int tt = t - 3;
        pp[t] = (tt >= 0 && tt < T) ? pr[tt] : 0.f;
    }
    const float* w = &Wl1[(o * C + i) * 7];
    float wk[7];
#pragma unroll
    for (int k = 0; k < 7; k++) wk[k] = w[k];

    float acc[T];
#pragma unroll
    for (int t = 0; t < T; t++) {
        float s = 0.f;
#pragma unroll
        for (int k = 0; k < 7; k++) s = fmaf(wk[k], pp[t + k], s);
        acc[t] = s;
    }
#pragma unroll
    for (int off = 16; off; off >>= 1) {
#pragma unroll
        for (int t = 0; t < T; t++) acc[t] += __shfl_xor_sync(0xFFFFFFFFu, acc[t], off);
    }
    __shared__ float sm[8][T];
    const int warp = i >> 5, lane = i & 31;
    if (lane < T) sm[warp][lane] = acc[lane];
    __syncthreads();
    if (i < T) {
        float s = 0.f;
#pragma unroll
        for (int w2 = 0; w2 < 8; w2++) s += sm[w2][i];
        g_y[(b * CO + o) * T + i] = tanhf(s);
    }
}

// ---------------------------------------------------------------------------
// Kernel 3: per-(b,c) warp computes the G softmax kernel and L sigmoid gate.
// grid = 2048/8 = 256 blocks, 256 threads.
// ---------------------------------------------------------------------------
__global__ void __launch_bounds__(256) gate_kernel(const float* __restrict__ W1,
                                                   const float* __restrict__ W2,
                                                   const float* __restrict__ Wl2) {
    const int gw = blockIdx.x * 8 + (threadIdx.x >> 5);
    const int lane = threadIdx.x & 31;
    const int b = gw >> 8, c = gw & 255;

    const float* pr = &g_pooled[(b * C + c) * T];
    float p = (lane < T) ? pr[lane] : 0.f;

    // --- G branch ---
    float g = 0.f;
#pragma unroll
    for (int t = 0; t < T; t++) {
        float pt = __shfl_sync(0xFFFFFFFFu, p, t);
        g = fmaf(W1[lane * T + t], pt, g);
    }
    g = tanhf(g);

    float lg[7];
#pragma unroll
    for (int k = 0; k < 7; k++) {
        float s = W2[k * 32 + lane] * g;
#pragma unroll
        for (int off = 16; off; off >>= 1) s += __shfl_xor_sync(0xFFFFFFFFu, s, off);
        lg[k] = s;
    }
    float m = lg[0];
#pragma unroll
    for (int k = 1; k < 7; k++) m = fmaxf(m, lg[k]);
    float den = 0.f;
#pragma unroll
    for (int k = 0; k < 7; k++) { lg[k] = expf(lg[k] - m); den += lg[k]; }
    float inv = 1.f / den;
    if (lane < 7) g_ker[(b * C + c) * 8 + lane] = lg[lane] * inv;

    // --- L branch ---
    float acc[T];
#pragma unroll
    for (int t = 0; t < T; t++) acc[t] = 0.f;
#pragma unroll
    for (int oo = 0; oo < 2; oo++) {
        int o = lane + 32 * oo;
        float w = Wl2[c * CO + o];
        const float* yr = &g_y[(b * CO + o) * T];
#pragma unroll
        for (int t = 0; t < T; t++) acc[t] = fmaf(w, yr[t], acc[t]);
    }
#pragma unroll
    for (int off = 16; off; off >>= 1) {
#pragma unroll
        for (int t = 0; t < T; t++) acc[t] += __shfl_xor_sync(0xFFFFFFFFu, acc[t], off);
    }
    if (lane < T) g_loc[(b * C + c) * T + lane] = 1.f / (1.f + expf(-acc[lane]));
}

// ---------------------------------------------------------------------------
// Kernel 4: gated depthwise temporal conv.  Flat mapping: column s = c*196+pix
// within a b; 256 cols per block; grid = 8*196 = 1568 (reversed for L2 reuse).
// Prologue is LOADS ONLY (no dot chains) -> low regs, short serial head.
// ---------------------------------------------------------------------------
__global__ void __launch_bounds__(256) tam_main_kernel(const float* __restrict__ x,
                                                       float* __restrict__ out) {
    const int blk = (int)gridDim.x - 1 - blockIdx.x;   // reverse order
    const int b  = blk / 196;
    const int j  = blk - b * 196;
    const int s0 = j * 256;
    const int c_first = s0 / HW4;

    __shared__ float sk[3][8];    // kernel[ci][k]
    __shared__ float sl[3][T];    // local[ci][t]

    const int warp = threadIdx.x >> 5;
    const int lane = threadIdx.x & 31;

    if (warp < 3) {
        const int c = c_first + warp;
        if (c < C) {
            const int bc = b * C + c;
            if (lane < 8)  sk[warp][lane] = g_ker[bc * 8 + lane];
            if (lane < T)  sl[warp][lane] = g_loc[bc * T + lane];
        }
    }
    __syncthreads();

    const int s  = s0 + threadIdx.x;        // column within b-slab
    const int c  = s / HW4;                 // constant divisor -> mul/shift
    const int ci = c - c_first;             // 0..2

    float ker[7], loc[T];
#pragma unroll
    for (int k = 0; k < 7; k++) ker[k] = sk[ci][k];
#pragma unroll
    for (int t = 0; t < T; t++) loc[t] = sl[ci][t];

    const size_t base = (size_t)(b * T) * SLAB + s;    // float4 index of (b,t=0,s)
    const float4* xp = reinterpret_cast<const float4*>(x);
    float4* op = reinterpret_cast<float4*>(out);

    float4 gt[T];
#pragma unroll
    for (int t = 0; t < T; t++) {
        float4 v = xp[base + (size_t)t * SLAB];
        float lt = loc[t];
        gt[t].x = v.x * lt; gt[t].y = v.y * lt;
        gt[t].z = v.z * lt; gt[t].w = v.w * lt;
    }
#pragma unroll
    for (int to = 0; to < T; to++) {
        float4 a = make_float4(0.f, 0.f, 0.f, 0.f);
#pragma unroll
        for (int k = 0; k < 7; k++) {
            int tt = to + k - 3;
            if (tt >= 0 && tt < T) {          // compile-time resolved
                float kv = ker[k];
                a.x = fmaf(kv, gt[tt].x, a.x);
                a.y = fmaf(kv, gt[tt].y, a.y);
                a.z = fmaf(kv, gt[tt].z, a.z);
                a.w = fmaf(kv, gt[tt].w, a.w);
            }
        }
        __stcs(&op[base + (size_t)to * SLAB], a);      // evict-first store
    }
}

// ---------------------------------------------------------------------------
extern "C" void kernel_launch(void* const* d_in, const int* in_sizes, int n_in,
                              void* d_out, int out_size) {
    const float* x   = (const float*)d_in[0];
    const float* W1  = (const float*)d_in[1];
    const float* W2  = (const float*)d_in[2];
    const float* Wl1 = (const float*)d_in[3];
    const float* Wl2 = (const float*)d_in[4];
    float* out = (float*)d_out;

    pool_kernel<<<(B * T * C) / 8, 256>>>(x);        // 4096 blocks
    conv1_kernel<<<B * CO, 256>>>(Wl1);              // 512 blocks
    gate_kernel<<<(B * C) / 8, 256>>>(W1, W2, Wl2);  // 256 blocks
    tam_main_kernel<<<B * 196, 256>>>(x, out);       // 1568 blocks
}

// round 17
// speedup vs baseline: 1.7666x; 1.0324x over previous
#include <cuda_runtime.h>
#include <math.h>

// ---------------------------------------------------------------------------
// TAM forward, GB300.  Shapes fixed: b=8, t=16, c=256, h=w=28 (784 px).
//   x   : [8,16,256,28,28] f32
//   W1  : [32,16]   W2 : [7,32]   Wl1 : [64,256,7]   Wl2 : [256,64,1]
//   out : [128,256,28,28] f32
// Pipeline (4 launches): pool -> conv1 -> gate -> main (streaming 7-tap conv)
// ---------------------------------------------------------------------------

#define B     8
#define T     16
#define C     256
#define HW4   196            // float4 per plane
#define SLAB  50176          // float4 per (b,t) slab  = C*HW4
#define CO    64             // c/4

__device__ float g_pooled[B * C * T];      // [b,c,t]
__device__ float g_y[B * CO * T];          // [b,o,t]
__device__ float g_ker[B * C * 8];         // [b,c,k] (k padded to 8)
__device__ float g_loc[B * C * T];         // [b,c,t]

// ---------------------------------------------------------------------------
// Kernel 1: pooled[b,c,t] = mean_{hw} x[b,t,c,hw].  One warp per plane.
// Measured: 19.5us, DRAM 69%, occ 86% -- at roofline, do not touch.
// ---------------------------------------------------------------------------
__global__ void __launch_bounds__(256) pool_kernel(const float* __restrict__ x) {
    const int warp = threadIdx.x >> 5;
    const int lane = threadIdx.x & 31;
    const int p = blockIdx.x * 8 + warp;           // p = (b*16+t)*256 + c
    const float4* xp = reinterpret_cast<const float4*>(x) + (size_t)p * HW4;

    float s = 0.f;
#pragma unroll
    for (int j = 0; j < 7; j++) {
        int idx = lane + 32 * j;
        if (idx < HW4) {
            float4 v = xp[idx];
            s += (v.x + v.y) + (v.z + v.w);
        }
    }
#pragma unroll
    for (int off = 16; off; off >>= 1) s += __shfl_xor_sync(0xFFFFFFFFu, s, off);

    if (lane == 0) {
        int c = p & 255;
        int bt = p >> 8;
        int t = bt & 15;
        int b = bt >> 4;
        g_pooled[(b * C + c) * T + t] = s * (1.f / 784.f);
    }
}

// ---------------------------------------------------------------------------
// Kernel 2: y[b,o,t] = tanh( sum_{i,k} Wl1[o,i,k] * pooled_pad[b,i,t+k-3] )
// grid = b*64 = 512 blocks, 256 threads (one thread per input channel i).
// ---------------------------------------------------------------------------
__global__ void __launch_bounds__(256) conv1_kernel(const float* __restrict__ Wl1) {
    const int b = blockIdx.x >> 6;
    const int o = blockIdx.x & 63;
    const int i = threadIdx.x;

    const float* pr = &g_pooled[(b * C + i) * T];
    float pp[T + 6];
#pragma unroll
    for (int t = 0; t < T + 6; t++) {
        int tt = t - 3;
        pp[t] = (tt >= 0 && tt < T) ? pr[tt] : 0.f;
    }
    const float* w = &Wl1[(o * C + i) * 7];
    float wk[7];
#pragma unroll
    for (int k = 0; k < 7; k++) wk[k] = w[k];

    float acc[T];
#pragma unroll
    for (int t = 0; t < T; t++) {
        float s = 0.f;
#pragma unroll
        for (int k = 0; k < 7; k++) s = fmaf(wk[k], pp[t + k], s);
        acc[t] = s;
    }
#pragma unroll
    for (int off = 16; off; off >>= 1) {
#pragma unroll
        for (int t = 0; t < T; t++) acc[t] += __shfl_xor_sync(0xFFFFFFFFu, acc[t], off);
    }
    __shared__ float sm[8][T];
    const int warp = i >> 5, lane = i & 31;
    if (lane < T) sm[warp][lane] = acc[lane];
    __syncthreads();
    if (i < T) {
        float s = 0.f;
#pragma unroll
        for (int w2 = 0; w2 < 8; w2++) s += sm[w2][i];
        g_y[(b * CO + o) * T + i] = tanhf(s);
    }
}

// ---------------------------------------------------------------------------
// Kernel 3: per-(b,c) warp computes the G softmax kernel and L sigmoid gate.
// grid = 2048/8 = 256 blocks, 256 threads.
// ---------------------------------------------------------------------------
__global__ void __launch_bounds__(256) gate_kernel(const float* __restrict__ W1,
                                                   const float* __restrict__ W2,
                                                   const float* __restrict__ Wl2) {
    const int gw = blockIdx.x * 8 + (threadIdx.x >> 5);
    const int lane = threadIdx.x & 31;
    const int b = gw >> 8, c = gw & 255;

    const float* pr = &g_pooled[(b * C + c) * T];
    float p = (lane < T) ? pr[lane] : 0.f;

    // --- G branch ---
    float g = 0.f;
#pragma unroll
    for (int t = 0; t < T; t++) {
        float pt = __shfl_sync(0xFFFFFFFFu, p, t);
        g = fmaf(W1[lane * T + t], pt, g);
    }
    g = tanhf(g);

    float lg[7];
#pragma unroll
    for (int k = 0; k < 7; k++) {
        float s = W2[k * 32 + lane] * g;
#pragma unroll
        for (int off = 16; off; off >>= 1) s += __shfl_xor_sync(0xFFFFFFFFu, s, off);
        lg[k] = s;
    }
    float m = lg[0];
#pragma unroll
    for (int k = 1; k < 7; k++) m = fmaxf(m, lg[k]);
    float den = 0.f;
#pragma unroll
    for (int k = 0; k < 7; k++) { lg[k] = expf(lg[k] - m); den += lg[k]; }
    float inv = 1.f / den;
    if (lane < 7) g_ker[(b * C + c) * 8 + lane] = lg[lane] * inv;

    // --- L branch ---
    float acc[T];
#pragma unroll
    for (int t = 0; t < T; t++) acc[t] = 0.f;
#pragma unroll
    for (int oo = 0; oo < 2; oo++) {
        int o = lane + 32 * oo;
        float w = Wl2[c * CO + o];
        const float* yr = &g_y[(b * CO + o) * T];
#pragma unroll
        for (int t = 0; t < T; t++) acc[t] = fmaf(w, yr[t], acc[t]);
    }
#pragma unroll
    for (int off = 16; off; off >>= 1) {
#pragma unroll
        for (int t = 0; t < T; t++) acc[t] += __shfl_xor_sync(0xFFFFFFFFu, acc[t], off);
    }
    if (lane < T) g_loc[(b * C + c) * T + lane] = 1.f / (1.f + expf(-acc[lane]));
}

// ---------------------------------------------------------------------------
// Kernel 4: gated depthwise temporal conv, STREAMING form.
// Iterate input planes tt once; each plane contributes to the <=7 output
// accumulators it feeds; store o[tt-3] as soon as complete.  Peak live state
// ~7 float4 accumulators + 1 input (vs 16 before) -> fewer regs, higher occ.
// Flat mapping: column s = c*196 + pix; 256 cols/block; grid reversed.
// ---------------------------------------------------------------------------
__global__ void __launch_bounds__(256) tam_main_kernel(const float* __restrict__ x,
                                                       float* __restrict__ out) {
    const int blk = (int)gridDim.x - 1 - blockIdx.x;   // reverse order
    const int b  = blk / 196;
    const int j  = blk - b * 196;
    const int s0 = j * 256;
    const int c_first = s0 / HW4;

    __shared__ float sk[3][8];    // kernel[ci][k]
    __shared__ float sl[3][T];    // local[ci][t]

    const int warp = threadIdx.x >> 5;
    const int lane = threadIdx.x & 31;

    if (warp < 3) {
        const int c = c_first + warp;
        if (c < C) {
            const int bc = b * C + c;
            if (lane < 8)  sk[warp][lane] = g_ker[bc * 8 + lane];
            if (lane < T)  sl[warp][lane] = g_loc[bc * T + lane];
        }
    }
    __syncthreads();

    const int s  = s0 + threadIdx.x;        // column within b-slab
    const int c  = s / HW4;                 // constant divisor -> mul/shift
    const int ci = c - c_first;             // 0..2

    float ker[7];
#pragma unroll
    for (int k = 0; k < 7; k++) ker[k] = sk[ci][k];

    const size_t base = (size_t)(b * T) * SLAB + s;    // float4 index of (b,t=0,s)
    const float4* xp = reinterpret_cast<const float4*>(x);
    float4* op = reinterpret_cast<float4*>(out);

    float4 o[T];   // straight-line unrolled: <=7 live at any point

#pragma unroll
    for (int tt = 0; tt < T; tt++) {
        float4 v = xp[base + (size_t)tt * SLAB];
        const float lt = sl[ci][tt];
        v.x *= lt; v.y *= lt; v.z *= lt; v.w *= lt;

        // scatter v into the outputs it feeds: to in [tt-3, tt+3],
        // coefficient ker[k] with k = tt - to + 3.
#pragma unroll
        for (int k = 0; k < 7; k++) {
            const int to = tt - k + 3;
            if (to >= 0 && to < T) {
                const int first_tt = (to - 3 > 0) ? (to - 3) : 0;  // compile-time
                const float kv = ker[k];
                if (tt == first_tt) {
                    o[to].x = kv * v.x;
                    o[to].y = kv * v.y;
                    o[to].z = kv * v.z;
                    o[to].w = kv * v.w;
                } else {
                    o[to].x = fmaf(kv, v.x, o[to].x);
                    o[to].y = fmaf(kv, v.y, o[to].y);
                    o[to].z = fmaf(kv, v.z, o[to].z);
                    o[to].w = fmaf(kv, v.w, o[to].w);
                }
            }
        }

        // o[tt-3] received its last contribution this iteration -> store it.
        if (tt >= 3) {
            __stcs(&op[base + (size_t)(tt - 3) * SLAB], o[tt - 3]);
        }
    }
    // tail: outputs 13,14,15 complete after tt=15
#pragma unroll
    for (int to = T - 3; to < T; to++) {
        __stcs(&op[base + (size_t)to * SLAB], o[to]);
    }
}

// ---------------------------------------------------------------------------
extern "C" void kernel_launch(void* const* d_in, const int* in_sizes, int n_in,
                              void* d_out, int out_size) {
    const float* x   = (const float*)d_in[0];
    const float* W1  = (const float*)d_in[1];
    const float* W2  = (const float*)d_in[2];
    const float* Wl1 = (const float*)d_in[3];
    const float* Wl2 = (const float*)d_in[4];
    float* out = (float*)d_out;

    pool_kernel<<<(B * T * C) / 8, 256>>>(x);        // 4096 blocks
    conv1_kernel<<<B * CO, 256>>>(Wl1);              // 512 blocks
    gate_kernel<<<(B * C) / 8, 256>>>(W1, W2, Wl2);  // 256 blocks
    tam_main_kernel<<<B * 196, 256>>>(x, out);       // 1568 blocks
}